// round 17
// baseline (speedup 1.0000x reference)
#include <cuda_runtime.h>
#include <cuda_fp16.h>
#include <cstdint>

// SpectralConv1D: out = irfft( pad( rfft(x)[:, :32, :] @ W ) )
// kA/kB: quad-folded scalar forward DFT + mix (proven R9 version).
// kCm:  inverse as mma.sync m16n8k16 HMMA GEMM (sm_80 path — harness target
//       is plain sm_100, no tcgen05). fp16 hi/lo split, 3 passes, f32 accum.
// B=64, S=4096, Cin=Cout=64, MODES=32.

#define S_TOT   4096
#define SMASK   4095
#define CIN     64
#define COUT    64
#define MODES   32
#define NB      64
#define CH_A    4
#define SUBS    4
#define NCH     (CH_A*SUBS)
#define QPB_A   256
#define STG_A   16
#define NSTG    (QPB_A/STG_A)

#define K2      64
#define G_SCALE 1024.0f
#define G_INV   (1.0f/1024.0f)

typedef unsigned long long ull;
typedef unsigned int uint32;

__device__ float2 g_tw2[1025][MODES];               // (cos,sin)(2*pi*s*k/4096)
__device__ float2 g_Yp[NCH][NB][MODES][CIN];        // split-K partials (Cr,Si)
__device__ float2 g_G[NB][MODES][COUT];             // mixed, scaled by G_SCALE/4096
__device__ __half g_Thi[S_TOT][K2];                 // T hi fp16 (cos k | sin k)
__device__ __half g_Tlo[S_TOT][K2];                 // T lo fp16

// ---- packed fp32x2 helpers ----
__device__ __forceinline__ float2 unpk(ull v) {
    float2 r; asm("mov.b64 {%0, %1}, %2;" : "=f"(r.x), "=f"(r.y) : "l"(v)); return r;
}
__device__ __forceinline__ void fma2(ull &acc, ull a, ull b) {
    asm("fma.rn.f32x2 %0, %1, %2, %0;" : "+l"(acc) : "l"(a), "l"(b));
}

__device__ __forceinline__ uint32 smem_to_u32(const void* p) {
    uint32 a;
    asm("{ .reg .u64 t; cvta.to.shared.u64 t, %1; cvt.u32.u64 %0, t; }"
        : "=r"(a) : "l"(p));
    return a;
}
#define SWZ(bo) ((bo) ^ (((bo) >> 3) & 0x70))

// ---- mma.sync / ldmatrix helpers (sm_80 baseline, valid on sm_100) ----
__device__ __forceinline__ void ldmat4(uint32* r, uint32 addr) {
    asm volatile("ldmatrix.sync.aligned.m8n8.x4.shared.b16 {%0,%1,%2,%3}, [%4];"
        : "=r"(r[0]), "=r"(r[1]), "=r"(r[2]), "=r"(r[3]) : "r"(addr));
}
__device__ __forceinline__ void mma16816(float* c, const uint32* a, const uint32* b) {
    asm volatile("mma.sync.aligned.m16n8k16.row.col.f32.f16.f16.f32 "
        "{%0,%1,%2,%3}, {%4,%5,%6,%7}, {%8,%9}, {%0,%1,%2,%3};"
        : "+f"(c[0]), "+f"(c[1]), "+f"(c[2]), "+f"(c[3])
        : "r"(a[0]), "r"(a[1]), "r"(a[2]), "r"(a[3]), "r"(b[0]), "r"(b[1]));
}

// ---- init kernels ----
__global__ void twiddle_init() {
    int j = blockIdx.x * blockDim.x + threadIdx.x;
    if (j < 1025 * MODES) {
        int s = j >> 5, k = j & 31;
        float sn, cs;
        sincospif((float)((s * k) & SMASK) * (1.0f / 2048.0f), &sn, &cs);
        g_tw2[s][k] = make_float2(cs, sn);
    }
}
__global__ void tsplit_init() {
    int j = blockIdx.x * blockDim.x + threadIdx.x;
    if (j < S_TOT * K2) {
        int s = j >> 6, k2 = j & 63, k = k2 & 31;
        float sn, cs;
        sincospif((float)((s * k) & SMASK) * (1.0f / 2048.0f), &sn, &cs);
        float v = (k2 < 32) ? cs : sn;
        __half hi = __float2half_rn(v);
        g_Thi[s][k2] = hi;
        g_Tlo[s][k2] = __float2half_rn(v - __half2float(hi));
    }
}

// ---- Stage 1 (quad-folded forward DFT, register-pipelined; R9 version) ----
__global__ void __launch_bounds__(256, 2) kA(const float* __restrict__ x) {
    __shared__ float2 cmb[2][2][STG_A][CIN];  // [buf][parity][s][i], 32 KB
    __shared__ float2 t2[2][STG_A][MODES];    // 8 KB
    int b = blockIdx.y, tid = threadIdx.x;
    int tx  = tid & 15;
    int kg  = (tid >> 4) & 3;
    int sub = tid >> 6;
    int k0 = kg * 8;
    int q00 = blockIdx.x * QPB_A;
    int r = tid >> 4, ig = tid & 15;
    int sl0 = tid >> 5, kk0 = tid & 31;

    ull acc[8][4];
#pragma unroll
    for (int a = 0; a < 8; a++)
#pragma unroll
        for (int c = 0; c < 4; c++) acc[a][c] = 0ull;

    const float* xb = x + (size_t)b * S_TOT * CIN;

    float4 a1, a2, a3, a4;
    float2 tw0, tw1;
    {
        int s = q00 + 1 + r;
        a1 = *(const float4*)&xb[(size_t)s * CIN + ig * 4];
        a2 = *(const float4*)&xb[(size_t)(2048 - s) * CIN + ig * 4];
        a3 = *(const float4*)&xb[(size_t)(2048 + s) * CIN + ig * 4];
        a4 = *(const float4*)&xb[(size_t)(4096 - s) * CIN + ig * 4];
        tw0 = g_tw2[q00 + 1 + sl0][kk0];
        tw1 = g_tw2[q00 + 1 + sl0 + 8][kk0];
    }

    for (int st = 0; st < NSTG; ++st) {
        int buf = st & 1;
        int q0 = q00 + st * STG_A;
        {
            int s = q0 + 1 + r;
            float h = (s == 1024) ? 0.5f : 1.0f;
            float x1[4] = {a1.x, a1.y, a1.z, a1.w};
            float x2[4] = {a2.x, a2.y, a2.z, a2.w};
            float x3[4] = {a3.x, a3.y, a3.z, a3.w};
            float x4[4] = {a4.x, a4.y, a4.z, a4.w};
            float pe[4], re[4], po[4], ro[4];
#pragma unroll
            for (int j = 0; j < 4; ++j) {
                float P = x1[j] + x4[j], Q = x2[j] + x3[j];
                float R2 = x1[j] - x4[j], T = x3[j] - x2[j];
                pe[j] = h * (P + Q); re[j] = h * (R2 + T);
                po[j] = h * (P - Q); ro[j] = h * (R2 - T);
            }
            *(float4*)&cmb[buf][0][r][ig * 4]     = make_float4(pe[0], re[0], pe[1], re[1]);
            *(float4*)&cmb[buf][0][r][ig * 4 + 2] = make_float4(pe[2], re[2], pe[3], re[3]);
            *(float4*)&cmb[buf][1][r][ig * 4]     = make_float4(po[0], ro[0], po[1], ro[1]);
            *(float4*)&cmb[buf][1][r][ig * 4 + 2] = make_float4(po[2], ro[2], po[3], ro[3]);
            t2[buf][sl0][kk0]     = tw0;
            t2[buf][sl0 + 8][kk0] = tw1;
        }
        __syncthreads();
        if (st + 1 < NSTG) {
            int s = q0 + STG_A + 1 + r;
            a1 = *(const float4*)&xb[(size_t)s * CIN + ig * 4];
            a2 = *(const float4*)&xb[(size_t)(2048 - s) * CIN + ig * 4];
            a3 = *(const float4*)&xb[(size_t)(2048 + s) * CIN + ig * 4];
            a4 = *(const float4*)&xb[(size_t)(4096 - s) * CIN + ig * 4];
            tw0 = g_tw2[q0 + STG_A + 1 + sl0][kk0];
            tw1 = g_tw2[q0 + STG_A + 1 + sl0 + 8][kk0];
        }
#pragma unroll
        for (int slr = 0; slr < 4; ++slr) {
            int sl = sub * 4 + slr;
            ull cE[4], cO[4];
#pragma unroll
            for (int ii = 0; ii < 4; ++ii) {
                cE[ii] = *(const ull*)&cmb[buf][0][sl][tx + 16 * ii];
                cO[ii] = *(const ull*)&cmb[buf][1][sl][tx + 16 * ii];
            }
            ull tt[8];
#pragma unroll
            for (int m = 0; m < 4; ++m) {
                ulonglong2 tp = *(const ulonglong2*)&t2[buf][sl][k0 + 2 * m];
                tt[2 * m] = tp.x; tt[2 * m + 1] = tp.y;
            }
#pragma unroll
            for (int kk = 0; kk < 8; ++kk)
#pragma unroll
                for (int ii = 0; ii < 4; ++ii)
                    fma2(acc[kk][ii], tt[kk], (kk & 1) ? cO[ii] : cE[ii]);
        }
    }
    int ch = blockIdx.x * SUBS + sub;
#pragma unroll
    for (int kk = 0; kk < 8; ++kk)
#pragma unroll
        for (int ii = 0; ii < 4; ++ii)
            g_Yp[ch][b][k0 + kk][tx + 16 * ii] = unpk(acc[kk][ii]);
}

// ---- Stage 2: reduce partials + rows {0,2048} + channel mix (scaled) ----
__global__ void __launch_bounds__(64) kB(const float* __restrict__ W,
                                         const float* __restrict__ x) {
    int k = blockIdx.x, b = blockIdx.y, o = threadIdx.x;
    __shared__ float2 cs[CIN];
    {
        float2 a = make_float2(0.f, 0.f);
#pragma unroll
        for (int c = 0; c < NCH; ++c) {
            float2 v = g_Yp[c][b][k][o];
            a.x += v.x; a.y += v.y;
        }
        float x0    = x[(size_t)b * S_TOT * CIN + o];
        float x2048 = x[(size_t)b * S_TOT * CIN + 2048 * CIN + o];
        a.x += x0 + ((k & 1) ? -x2048 : x2048);
        cs[o] = a;
    }
    __syncthreads();
    const float* Wk = W + (size_t)k * CIN * COUT + o;
    float gc = 0.f, gs = 0.f;
#pragma unroll 8
    for (int i = 0; i < CIN; ++i) {
        float w = Wk[i * COUT];
        float2 v = cs[i];
        gc = fmaf(v.x, w, gc);
        gs = fmaf(v.y, w, gs);
    }
    float a = (k == 0 ? 1.0f : 2.0f) * (G_SCALE / (float)S_TOT);
    g_G[b][k][o] = make_float2(gc * a, gs * a);
}

// ---- Stage 3: HMMA inverse ----
// Out[s,o] = sum_k2 T[s,k2]*H[k2,o]. Block: 128 s-rows x all 64 o.
// Warps: 4 n-columns (16 o each) x 2 m-halves (64 rows). 3-pass fp16 split.
#define SMC_GSH 0                      // float2 [32][64] = 16 KB (staged G)
#define SMC_THI 16384                  // 128 rows x 128 B (swizzled)
#define SMC_TLO 32768
#define SMC_TOT 49152

__global__ void __launch_bounds__(256) kCm(float* __restrict__ out) {
    extern __shared__ __align__(1024) unsigned char smem[];
    uint32 sb = smem_to_u32(smem);
    int tid = threadIdx.x;
    int b = blockIdx.y, mc = blockIdx.x;      // m0 = mc*128
    int m0 = mc * 128;

    // stage G (16 KB) and T tiles (16 KB hi + 16 KB lo, SW128-style swizzle)
    {
        const uint4* gs = (const uint4*)&g_G[b][0][0];
        uint4* gd = (uint4*)(smem + SMC_GSH);
#pragma unroll
        for (int t = 0; t < 4; ++t) gd[tid + t * 256] = gs[tid + t * 256];
#pragma unroll
        for (int t = 0; t < 4; ++t) {
            int u = tid + t * 256;
            int r = u >> 3, cb = u & 7;
            uint4 vh = ((const uint4*)&g_Thi[m0 + r][0])[cb];
            uint4 vl = ((const uint4*)&g_Tlo[m0 + r][0])[cb];
            uint32 so = SWZ((uint32)(r * 128 + cb * 16));
            *(uint4*)(smem + SMC_THI + so) = vh;
            *(uint4*)(smem + SMC_TLO + so) = vl;
        }
    }
    __syncthreads();

    int w = tid >> 5, l = tid & 31;
    int nw = w & 3, mh = w >> 2;              // n-column, m-half
    int n0 = nw * 16;
    int t4 = l & 3, gn = l >> 2;

    // Build B fragments from staged G (hi/lo split on the fly).
    // m16n8k16 col B frag: reg j holds halves (k2 = 2*t4 + 8*j, +1), col gn.
    uint32 Bhi[4][2][2], Blo[4][2][2];
#pragma unroll
    for (int kf = 0; kf < 4; ++kf) {
        bool isSin = (kf >= 2);
#pragma unroll
        for (int nf = 0; nf < 2; ++nf) {
            int o = n0 + 8 * nf + gn;
#pragma unroll
            for (int j = 0; j < 2; ++j) {
                int k2 = 16 * kf + 2 * t4 + 8 * j;
                int km = isSin ? (k2 - 32) : k2;
                float2 f0 = *(const float2*)(smem + SMC_GSH + ((km)     * 64 + o) * 8);
                float2 f1 = *(const float2*)(smem + SMC_GSH + ((km + 1) * 64 + o) * 8);
                float v0 = isSin ? f0.y : f0.x;
                float v1 = isSin ? f1.y : f1.x;
                __half h0 = __float2half_rn(v0), h1 = __float2half_rn(v1);
                __half l0 = __float2half_rn(v0 - __half2float(h0));
                __half l1 = __float2half_rn(v1 - __half2float(h1));
                __half2 ph = __halves2half2(h0, h1), pl = __halves2half2(l0, l1);
                Bhi[kf][nf][j] = *(const uint32*)&ph;
                Blo[kf][nf][j] = *(const uint32*)&pl;
            }
        }
    }

    // ldmatrix lane address components (row-local, col bytes)
    int lrow = (l & 15);
    int lcol16 = ((l >> 4) & 1) * 16;

#pragma unroll
    for (int mt = 0; mt < 4; ++mt) {
        int mrl = mh * 64 + mt * 16;          // tile-local base row
        uint32 Ahi[4][4], Alo[4][4];
#pragma unroll
        for (int kf = 0; kf < 4; ++kf) {
            uint32 off = SWZ((uint32)((mrl + lrow) * 128 + 32 * kf + lcol16));
            ldmat4(Ahi[kf], sb + SMC_THI + off);
            ldmat4(Alo[kf], sb + SMC_TLO + off);
        }
        float acc[2][4];
#pragma unroll
        for (int nf = 0; nf < 2; ++nf)
#pragma unroll
            for (int c = 0; c < 4; ++c) acc[nf][c] = 0.f;
#pragma unroll
        for (int kf = 0; kf < 4; ++kf)
#pragma unroll
            for (int nf = 0; nf < 2; ++nf) {
                mma16816(acc[nf], Ahi[kf], Bhi[kf][nf]);
                mma16816(acc[nf], Ahi[kf], Blo[kf][nf]);
                mma16816(acc[nf], Alo[kf], Bhi[kf][nf]);
            }
        // store: D frag rows gn, gn+8; cols 2*t4, 2*t4+1
        int mrow = m0 + mrl;
        float* ob = out + ((size_t)b * S_TOT + mrow) * COUT;
#pragma unroll
        for (int nf = 0; nf < 2; ++nf) {
            int oc = n0 + 8 * nf + 2 * t4;
            *(float2*)&ob[(size_t)gn * COUT + oc] =
                make_float2(acc[nf][0] * G_INV, acc[nf][1] * G_INV);
            *(float2*)&ob[(size_t)(gn + 8) * COUT + oc] =
                make_float2(acc[nf][2] * G_INV, acc[nf][3] * G_INV);
        }
    }
}

extern "C" void kernel_launch(void* const* d_in, const int* in_sizes, int n_in,
                              void* d_out, int out_size) {
    const float* x = (const float*)d_in[0];   // [64, 4096, 64]
    const float* W = (const float*)d_in[1];   // [32, 64, 64]
    float* out = (float*)d_out;               // [64, 4096, 64]
    (void)in_sizes; (void)n_in; (void)out_size;

    cudaFuncSetAttribute(kCm, cudaFuncAttributeMaxDynamicSharedMemorySize, SMC_TOT);

    twiddle_init<<<129, 256>>>();
    tsplit_init<<<(S_TOT * K2 + 255) / 256, 256>>>();
    kA<<<dim3(CH_A, NB), 256>>>(x);
    kB<<<dim3(MODES, NB), 64>>>(W, x);
    kCm<<<dim3(S_TOT / 128, NB), 256, SMC_TOT>>>(out);
}